// round 12
// baseline (speedup 1.0000x reference)
#include <cuda_runtime.h>
#include <math.h>

#define NW 10
#define NP 5                  // wire pairs
#define NQ 4                  // quantities per pair: cc, cs, sc, ss
#define NSAMP 4096
#define TM 128                // X rows per CTA
#define TN 128                // Y cols per CTA

typedef unsigned long long u64;

// out[x, y] = prod_i cos^2((X[x,i] - Y[y,i]) / 2)
// (unitary invariance: shared-params RZ/CNOT circuit cancels in <psi_x|psi_y>;
//  product-state overlap factorizes per qubit. Wire-pair expansion:
//  (ci*cyi + si*syi)(cj*cyj + sj*syj) = cc*CC + cs*CS + sc*SC + ss*SS.)

// global pair-product tables (device-code references ONLY)
__device__ float g_Xq[NP * NQ][NSAMP];
__device__ float g_Yq[NP * NQ][NSAMP];

__device__ __forceinline__ u64 pack2(float a) {
    u64 r; asm("mov.b64 %0, {%1, %1};" : "=l"(r) : "f"(a)); return r;
}
__device__ __forceinline__ u64 mul2(u64 a, u64 b) {
    u64 r; asm("mul.rn.f32x2 %0, %1, %2;" : "=l"(r) : "l"(a), "l"(b)); return r;
}
__device__ __forceinline__ u64 fma2(u64 a, u64 b, u64 c) {
    u64 r; asm("fma.rn.f32x2 %0, %1, %2, %3;" : "=l"(r) : "l"(a), "l"(b), "l"(c)); return r;
}

// one thread per sample: build pair-product tables for both sides
__global__ void tab_kernel(const float* __restrict__ X, const float* __restrict__ Y) {
    const int s = blockIdx.x * 256 + threadIdx.x;
#pragma unroll
    for (int p = 0; p < NP; ++p) {
        float si, ci, sj, cj;
        __sincosf(0.5f * X[s * NW + 2 * p],     &si, &ci);
        __sincosf(0.5f * X[s * NW + 2 * p + 1], &sj, &cj);
        g_Xq[p * NQ + 0][s] = ci * cj;
        g_Xq[p * NQ + 1][s] = ci * sj;
        g_Xq[p * NQ + 2][s] = si * cj;
        g_Xq[p * NQ + 3][s] = si * sj;
        __sincosf(0.5f * Y[s * NW + 2 * p],     &si, &ci);
        __sincosf(0.5f * Y[s * NW + 2 * p + 1], &sj, &cj);
        g_Yq[p * NQ + 0][s] = ci * cj;
        g_Yq[p * NQ + 1][s] = ci * sj;
        g_Yq[p * NQ + 2][s] = si * cj;
        g_Yq[p * NQ + 3][s] = si * sj;
    }
}

#define ROWCHUNKS (TM / 4)                 // 32 float4 per (p,q) row
#define SIDECHUNKS (NP * NQ * ROWCHUNKS)   // 640 per side

__global__ void __launch_bounds__(256, 2)
qk_kernel(float* __restrict__ out) {
    __shared__ __align__(16) float sx[NP * NQ][TM];
    __shared__ __align__(16) float sy[NP * NQ][TN];

    const int tid = threadIdx.x;
    const int bn = blockIdx.x * TN;     // Y cols
    const int bm = blockIdx.y * TM;     // X rows

    // prologue: pure coalesced copies of precomputed tables
    {
        float4* dx = (float4*)sx;
        float4* dy = (float4*)sy;
        for (int c = tid; c < 2 * SIDECHUNKS; c += 256) {
            if (c < SIDECHUNKS) {
                int pq = c >> 5, off = c & 31;
                dx[pq * ROWCHUNKS + off] = ((const float4*)(&g_Xq[pq][bm]))[off];
            } else {
                int c2 = c - SIDECHUNKS;
                int pq = c2 >> 5, off = c2 & 31;
                dy[pq * ROWCHUNKS + off] = ((const float4*)(&g_Yq[pq][bn]))[off];
            }
        }
    }
    __syncthreads();

    const int tx = tid & 15;            // col group: 8 cols = 4 packs
    const int ty = tid >> 4;            // row group: 8 rows
    const int r0 = ty * 8;
    const int c0 = tx * 8;

    u64 acc[8][4];

#pragma unroll
    for (int p = 0; p < NP; ++p) {
        // y side: 4 quantities x 8 cols = 4 packs each (2 LDS.128 per q)
        u64 y[NQ][4];
#pragma unroll
        for (int q = 0; q < NQ; ++q) {
            ulonglong2 a = *(const ulonglong2*)&sy[p * NQ + q][c0];
            ulonglong2 b = *(const ulonglong2*)&sy[p * NQ + q][c0 + 4];
            y[q][0] = a.x; y[q][1] = a.y; y[q][2] = b.x; y[q][3] = b.y;
        }
        // x side in two 4-row halves (register pressure)
#pragma unroll
        for (int h = 0; h < 2; ++h) {
            float xq[NQ][4];
#pragma unroll
            for (int q = 0; q < NQ; ++q) {
                float4 v = *(const float4*)&sx[p * NQ + q][r0 + 4 * h];
                xq[q][0] = v.x; xq[q][1] = v.y; xq[q][2] = v.z; xq[q][3] = v.w;
            }
#pragma unroll
            for (int r = 0; r < 4; ++r) {
                u64 x0 = pack2(xq[0][r]);
                u64 x1 = pack2(xq[1][r]);
                u64 x2 = pack2(xq[2][r]);
                u64 x3 = pack2(xq[3][r]);
                const int rr = 4 * h + r;
#pragma unroll
                for (int c = 0; c < 4; ++c) {
                    u64 t = mul2(x0, y[0][c]);
                    t = fma2(x1, y[1][c], t);
                    t = fma2(x2, y[2][c], t);
                    t = fma2(x3, y[3][c], t);
                    acc[rr][c] = (p == 0) ? t : mul2(acc[rr][c], t);
                }
            }
        }
    }

    // epilogue: square packed, two 16B stores per row
#pragma unroll
    for (int r = 0; r < 8; ++r) {
        float* orow = out + (size_t)(bm + r0 + r) * NSAMP + bn + c0;
        ulonglong2 v0, v1;
        v0.x = mul2(acc[r][0], acc[r][0]);
        v0.y = mul2(acc[r][1], acc[r][1]);
        v1.x = mul2(acc[r][2], acc[r][2]);
        v1.y = mul2(acc[r][3], acc[r][3]);
        *(ulonglong2*)(orow)     = v0;
        *(ulonglong2*)(orow + 4) = v1;
    }
}

extern "C" void kernel_launch(void* const* d_in, const int* in_sizes, int n_in,
                              void* d_out, int out_size) {
    const float* X = (const float*)d_in[0];      // (4096, 10)
    const float* Y = (const float*)d_in[1];      // (4096, 10)
    // d_in[2] (params) provably does not affect the output (unitary invariance)
    float* out = (float*)d_out;                  // (4096, 4096)

    tab_kernel<<<NSAMP / 256, 256>>>(X, Y);

    dim3 grid(NSAMP / TN, NSAMP / TM);           // (32, 32)
    qk_kernel<<<grid, 256>>>(out);
}

// round 13
// speedup vs baseline: 1.1393x; 1.1393x over previous
#include <cuda_runtime.h>
#include <math.h>

#define NW 10
#define NP 5                  // wire pairs
#define NQ 4                  // quantities per pair: cc, cs, sc, ss
#define NSAMP 4096
#define TMC 64                // X rows per CTA (8 warps x 8 rows)
#define TNC 64                // Y cols per CTA (lane, lane+32)

typedef unsigned long long u64;

// out[x, y] = prod_i cos^2((X[x,i] - Y[y,i]) / 2)
// (unitary invariance: shared-params RZ/CNOT circuit cancels in <psi_x|psi_y>;
//  product-state overlap factorizes per qubit. Wire-pair expansion:
//  (ci*cyi + si*syi)(cj*cyj + sj*syj) = cc*CC + cs*CS + sc*SC + ss*SS.)

// global pair-product tables (device-code references ONLY)
__device__ float g_Xp[NP][NQ][NSAMP];       // x side: (p,q)-major rows
__device__ float g_Yp[NSAMP][NP * NQ];      // y side: sample-major, 20 floats/row

__device__ __forceinline__ u64 dup2(float a) {
    u64 r; asm("mov.b64 %0, {%1, %1};" : "=l"(r) : "f"(a)); return r;
}
__device__ __forceinline__ u64 mul2(u64 a, u64 b) {
    u64 r; asm("mul.rn.f32x2 %0, %1, %2;" : "=l"(r) : "l"(a), "l"(b)); return r;
}
__device__ __forceinline__ u64 fma2(u64 a, u64 b, u64 c) {
    u64 r; asm("fma.rn.f32x2 %0, %1, %2, %3;" : "=l"(r) : "l"(a), "l"(b), "l"(c)); return r;
}
__device__ __forceinline__ void unpk(u64 v, float& lo, float& hi) {
    asm("mov.b64 {%0, %1}, %2;" : "=f"(lo), "=f"(hi) : "l"(v));
}

// one thread per sample: build pair-product tables for both sides
__global__ void tab_kernel(const float* __restrict__ X, const float* __restrict__ Y) {
    const int s = blockIdx.x * 256 + threadIdx.x;
#pragma unroll
    for (int p = 0; p < NP; ++p) {
        float si, ci, sj, cj;
        __sincosf(0.5f * X[s * NW + 2 * p],     &si, &ci);
        __sincosf(0.5f * X[s * NW + 2 * p + 1], &sj, &cj);
        g_Xp[p][0][s] = ci * cj;
        g_Xp[p][1][s] = ci * sj;
        g_Xp[p][2][s] = si * cj;
        g_Xp[p][3][s] = si * sj;
        __sincosf(0.5f * Y[s * NW + 2 * p],     &si, &ci);
        __sincosf(0.5f * Y[s * NW + 2 * p + 1], &sj, &cj);
        g_Yp[s][p * NQ + 0] = ci * cj;
        g_Yp[s][p * NQ + 1] = ci * sj;
        g_Yp[s][p * NQ + 2] = si * cj;
        g_Yp[s][p * NQ + 3] = si * sj;
    }
}

#define XCH (NP * NQ * TMC / 4)    // 320 float4 chunks
#define YCH (TNC * NP * NQ / 4)    // 320 float4 chunks

__global__ void __launch_bounds__(256, 4)
qk_kernel(float* __restrict__ out) {
    __shared__ __align__(16) float sx[NP][NQ][TMC];      // 5 KB
    __shared__ __align__(16) float sy[TNC][NP * NQ];     // 5 KB (80B rows)

    const int tid = threadIdx.x;
    const int bn = blockIdx.x * TNC;    // Y cols
    const int bm = blockIdx.y * TMC;    // X rows

    // prologue: pure coalesced float4 copies of precomputed tables
    {
        float4* dx = (float4*)sx;
        float4* dy = (float4*)sy;
        const float* gx = &g_Xp[0][0][0];
        for (int c = tid; c < XCH + YCH; c += 256) {
            if (c < XCH) {
                int pq = c >> 4, off = c & 15;   // 16 chunks per (p,q) row
                dx[c] = ((const float4*)(gx + pq * NSAMP + bm))[off];
            } else {
                int c2 = c - XCH;                // 5 chunks per sample row
                dy[c2] = ((const float4*)(&g_Yp[bn + c2 / 5][0]))[c2 % 5];
            }
        }
    }
    __syncthreads();

    const int warp = tid >> 5;
    const int lane = tid & 31;
    const int r0 = warp * 8;            // warp-uniform 8-row block
    // cols: bn + lane  and  bn + lane + 32

    u64 acc[4][2];                      // [row-pack][col]

#pragma unroll
    for (int p = 0; p < NP; ++p) {
        // y side: 4 quantities per col, one LDS.128 per col, dup-packed
        float4 ya = *(const float4*)&sy[lane][p * NQ];
        float4 yb = *(const float4*)&sy[lane + 32][p * NQ];
        u64 y0[NQ] = {dup2(ya.x), dup2(ya.y), dup2(ya.z), dup2(ya.w)};
        u64 y1[NQ] = {dup2(yb.x), dup2(yb.y), dup2(yb.z), dup2(yb.w)};

        // x side: rows adjacent in memory -> LDS.128 = 2 natural f32x2 packs,
        // warp-uniform address -> pure broadcast. Two 4-row halves.
#pragma unroll
        for (int h = 0; h < 2; ++h) {
            u64 xq[NQ][2];
#pragma unroll
            for (int q = 0; q < NQ; ++q) {
                ulonglong2 v = *(const ulonglong2*)&sx[p][q][r0 + 4 * h];
                xq[q][0] = v.x; xq[q][1] = v.y;
            }
#pragma unroll
            for (int k = 0; k < 2; ++k) {
                const int kk = 2 * h + k;
                u64 t0 = mul2(xq[0][k], y0[0]);
                t0 = fma2(xq[1][k], y0[1], t0);
                t0 = fma2(xq[2][k], y0[2], t0);
                t0 = fma2(xq[3][k], y0[3], t0);
                u64 t1 = mul2(xq[0][k], y1[0]);
                t1 = fma2(xq[1][k], y1[1], t1);
                t1 = fma2(xq[2][k], y1[2], t1);
                t1 = fma2(xq[3][k], y1[3], t1);
                if (p == 0) { acc[kk][0] = t0; acc[kk][1] = t1; }
                else        { acc[kk][0] = mul2(acc[kk][0], t0);
                              acc[kk][1] = mul2(acc[kk][1], t1); }
            }
        }
    }

    // epilogue: square, unpack row-pairs, coalesced scalar stores
#pragma unroll
    for (int k = 0; k < 4; ++k) {
        const int row = bm + r0 + 2 * k;
#pragma unroll
        for (int c = 0; c < 2; ++c) {
            u64 sq = mul2(acc[k][c], acc[k][c]);
            float lo, hi;
            unpk(sq, lo, hi);
            const int col = bn + lane + 32 * c;
            out[(size_t)row * NSAMP + col] = lo;
            out[(size_t)(row + 1) * NSAMP + col] = hi;
        }
    }
}

extern "C" void kernel_launch(void* const* d_in, const int* in_sizes, int n_in,
                              void* d_out, int out_size) {
    const float* X = (const float*)d_in[0];      // (4096, 10)
    const float* Y = (const float*)d_in[1];      // (4096, 10)
    // d_in[2] (params) provably does not affect the output (unitary invariance)
    float* out = (float*)d_out;                  // (4096, 4096)

    tab_kernel<<<NSAMP / 256, 256>>>(X, Y);

    dim3 grid(NSAMP / TNC, NSAMP / TMC);         // (64, 64)
    qk_kernel<<<grid, 256>>>(out);
}

// round 14
// speedup vs baseline: 1.2000x; 1.0533x over previous
#include <cuda_runtime.h>
#include <math.h>

#define NW 10
#define NP 5                  // wire pairs
#define NQ 4                  // quantities per pair: cc, cs, sc, ss
#define NSAMP 4096
#define TMC 64                // X rows per CTA (8 warps x 8 rows)
#define TNC 64                // Y cols per CTA (lane, lane+32)
#define YPAD 28               // padded y row stride (floats): conflict-free LDS.128

typedef unsigned long long u64;

// out[x, y] = prod_i cos^2((X[x,i] - Y[y,i]) / 2)
// (unitary invariance: shared-params RZ/CNOT circuit cancels in <psi_x|psi_y>;
//  product-state overlap factorizes per qubit. Wire-pair expansion:
//  (ci*cyi + si*syi)(cj*cyj + sj*syj) = cc*CC + cs*CS + sc*SC + ss*SS.)

// global pair-product tables (device-code references ONLY)
__device__ float g_Xp[NP][NQ][NSAMP];       // x side: (p,q)-major rows
__device__ float g_Yp[NSAMP][NP * NQ];      // y side: sample-major, 20 floats/row

__device__ __forceinline__ u64 dup2(float a) {
    u64 r; asm("mov.b64 %0, {%1, %1};" : "=l"(r) : "f"(a)); return r;
}
__device__ __forceinline__ u64 mul2(u64 a, u64 b) {
    u64 r; asm("mul.rn.f32x2 %0, %1, %2;" : "=l"(r) : "l"(a), "l"(b)); return r;
}
__device__ __forceinline__ u64 fma2(u64 a, u64 b, u64 c) {
    u64 r; asm("fma.rn.f32x2 %0, %1, %2, %3;" : "=l"(r) : "l"(a), "l"(b), "l"(c)); return r;
}
__device__ __forceinline__ void unpk(u64 v, float& lo, float& hi) {
    asm("mov.b64 {%0, %1}, %2;" : "=f"(lo), "=f"(hi) : "l"(v));
}

// one thread per (pair, sample): 20480 threads, coalesced x-table writes
__global__ void tab_kernel(const float* __restrict__ X, const float* __restrict__ Y) {
    const int t = blockIdx.x * 256 + threadIdx.x;
    const int p = t >> 12;          // 0..4 (consecutive threads share p)
    const int s = t & 4095;
    float si, ci, sj, cj;
    __sincosf(0.5f * X[s * NW + 2 * p],     &si, &ci);
    __sincosf(0.5f * X[s * NW + 2 * p + 1], &sj, &cj);
    g_Xp[p][0][s] = ci * cj;
    g_Xp[p][1][s] = ci * sj;
    g_Xp[p][2][s] = si * cj;
    g_Xp[p][3][s] = si * sj;
    __sincosf(0.5f * Y[s * NW + 2 * p],     &si, &ci);
    __sincosf(0.5f * Y[s * NW + 2 * p + 1], &sj, &cj);
    g_Yp[s][p * NQ + 0] = ci * cj;
    g_Yp[s][p * NQ + 1] = ci * sj;
    g_Yp[s][p * NQ + 2] = si * cj;
    g_Yp[s][p * NQ + 3] = si * sj;
}

#define XCH (NP * NQ * TMC / 4)    // 320 float4 chunks
#define YCH (TNC * NP)             // 320 float4 chunks (5 per col row)

__global__ void __launch_bounds__(256, 4)
qk_kernel(float* __restrict__ out) {
    __shared__ __align__(16) float sx[NP][NQ][TMC];      // 5 KB
    __shared__ __align__(16) float sy[TNC][YPAD];        // 7 KB, 112B rows

    const int tid = threadIdx.x;
    const int bn = blockIdx.x * TNC;    // Y cols
    const int bm = blockIdx.y * TMC;    // X rows

    // prologue: pure coalesced float4 copies of precomputed tables
    {
        float4* dx = (float4*)sx;
        float4* dy = (float4*)sy;
        const float* gx = &g_Xp[0][0][0];
        for (int c = tid; c < XCH + YCH; c += 256) {
            if (c < XCH) {
                int pq = c >> 4, off = c & 15;   // 16 chunks per (p,q) row
                dx[c] = ((const float4*)(gx + pq * NSAMP + bm))[off];
            } else {
                int c2 = c - XCH;                // 5 chunks per col row
                int col = c2 / 5, j = c2 - 5 * col;
                dy[col * (YPAD / 4) + j] = ((const float4*)(&g_Yp[bn + col][0]))[j];
            }
        }
    }
    __syncthreads();

    const int warp = tid >> 5;
    const int lane = tid & 31;
    const int r0 = warp * 8;            // warp-uniform 8-row block
    // cols: bn + lane  and  bn + lane + 32

    u64 acc[4][2];                      // [row-pack][col]

#pragma unroll
    for (int p = 0; p < NP; ++p) {
        // y side: stride-28 rows -> conflict-free LDS.128; dup-pack per quantity
        float4 ya = *(const float4*)&sy[lane][p * NQ];
        float4 yb = *(const float4*)&sy[lane + 32][p * NQ];
        u64 y0[NQ] = {dup2(ya.x), dup2(ya.y), dup2(ya.z), dup2(ya.w)};
        u64 y1[NQ] = {dup2(yb.x), dup2(yb.y), dup2(yb.z), dup2(yb.w)};

        // x side: rows adjacent in memory -> LDS.128 = 2 natural f32x2 packs,
        // warp-uniform address -> pure broadcast. Two 4-row halves.
#pragma unroll
        for (int h = 0; h < 2; ++h) {
            u64 xq[NQ][2];
#pragma unroll
            for (int q = 0; q < NQ; ++q) {
                ulonglong2 v = *(const ulonglong2*)&sx[p][q][r0 + 4 * h];
                xq[q][0] = v.x; xq[q][1] = v.y;
            }
#pragma unroll
            for (int k = 0; k < 2; ++k) {
                const int kk = 2 * h + k;
                u64 t0 = mul2(xq[0][k], y0[0]);
                t0 = fma2(xq[1][k], y0[1], t0);
                t0 = fma2(xq[2][k], y0[2], t0);
                t0 = fma2(xq[3][k], y0[3], t0);
                u64 t1 = mul2(xq[0][k], y1[0]);
                t1 = fma2(xq[1][k], y1[1], t1);
                t1 = fma2(xq[2][k], y1[2], t1);
                t1 = fma2(xq[3][k], y1[3], t1);
                if (p == 0) { acc[kk][0] = t0; acc[kk][1] = t1; }
                else        { acc[kk][0] = mul2(acc[kk][0], t0);
                              acc[kk][1] = mul2(acc[kk][1], t1); }
            }
        }
    }

    // epilogue: square, unpack row-pairs, coalesced scalar stores
#pragma unroll
    for (int k = 0; k < 4; ++k) {
        const int row = bm + r0 + 2 * k;
#pragma unroll
        for (int c = 0; c < 2; ++c) {
            u64 sq = mul2(acc[k][c], acc[k][c]);
            float lo, hi;
            unpk(sq, lo, hi);
            const int col = bn + lane + 32 * c;
            out[(size_t)row * NSAMP + col] = lo;
            out[(size_t)(row + 1) * NSAMP + col] = hi;
        }
    }
}

extern "C" void kernel_launch(void* const* d_in, const int* in_sizes, int n_in,
                              void* d_out, int out_size) {
    const float* X = (const float*)d_in[0];      // (4096, 10)
    const float* Y = (const float*)d_in[1];      // (4096, 10)
    // d_in[2] (params) provably does not affect the output (unitary invariance)
    float* out = (float*)d_out;                  // (4096, 4096)

    tab_kernel<<<NP * NSAMP / 256, 256>>>(X, Y);   // 80 CTAs

    dim3 grid(NSAMP / TNC, NSAMP / TMC);           // (64, 64)
    qk_kernel<<<grid, 256>>>(out);
}